// round 4
// baseline (speedup 1.0000x reference)
#include <cuda_runtime.h>
#include <math.h>

#define N_BATCH 8192
#define DIM 16
#define HID 800
#define KB 32
#define M3 95   /* 3*K_BINS - 1 */

// ---------------- scratch (static device allocations; no cudaMalloc) -------
static __device__ __align__(16) float g_F [(size_t)DIM * N_BATCH * KB];   // trig features, zero-padded per-dim
static __device__ __align__(16) float g_H1[(size_t)DIM * N_BATCH * HID];  // layer1 activations
static __device__ __align__(16) float g_H2[(size_t)DIM * N_BATCH * HID];  // layer2 activations
static __device__ __align__(16) float g_O3[(size_t)DIM * N_BATCH * M3];   // layer3 pre-spline
static __device__ float g_LD[DIM * N_BATCH];                              // per-dim logdet parts

// ---------------- kernel 1: trig featurization ------------------------------
// F[i][n][j] encodes the reference's concat(cos(pi*x[:, :i]/3), sin(...)) with
// zero padding to K=32 so layer1 is a uniform K=32 GEMM.  i==0 uses the
// constant feature (cos(0)=1, sin(0)=0).
__global__ void featurize_kernel(const float* __restrict__ x) {
    int gid = blockIdx.x * blockDim.x + threadIdx.x;
    const int total = DIM * N_BATCH * KB;
    if (gid >= total) return;
    int j    = gid & 31;
    int rest = gid >> 5;
    int n    = rest & (N_BATCH - 1);
    int i    = rest >> 13;             // N_BATCH = 2^13

    float v = 0.0f;
    const float PI = 3.14159265358979323846f;
    if (i == 0) {
        v = (j == 0) ? 1.0f : 0.0f;
    } else if (j < i) {
        v = cosf((PI * x[n * DIM + j]) / 3.0f);
    } else if (j < 2 * i) {
        v = sinf((PI * x[n * DIM + (j - i)]) / 3.0f);
    }
    g_F[gid] = v;
}

// ---------------- kernel 2: batched GEMM + bias + optional tanh -------------
// C[dim][n][m] = act( sum_k A[dim][n][k] * W[dim][k][m] + b[dim][m] )
// Tile: 128 (batch) x 64 (out) x 16 (k). 256 threads, 8x4 per thread.
__global__ __launch_bounds__(256) void gemm_bias_act(
    const float* __restrict__ A, const float* __restrict__ W,
    const float* __restrict__ bias, float* __restrict__ C,
    int Ktot, int M, int act)
{
    const int dim = blockIdx.z;
    const float* Ad = A + (size_t)dim * N_BATCH * Ktot;
    const float* Wd = W + (size_t)dim * Ktot * M;
    const float* bd = bias + dim * M;
    float* Cd = C + (size_t)dim * N_BATCH * M;

    const int n0 = blockIdx.y * 128;
    const int m0 = blockIdx.x * 64;

    __shared__ float As[16][132];   // [k][n-row], +4 pad keeps 16B alignment
    __shared__ float Bs[16][64];    // [k][m-col]

    const int tid = threadIdx.x;
    const int tx = tid & 15;        // -> 4 output cols
    const int ty = tid >> 4;        // -> 8 output rows

    const int a_row0 = tid >> 2;            // 0..63 (+64 for second vector)
    const int a_kq   = (tid & 3) * 4;       // k offset within tile
    const int b_mc   = tid & 63;
    const int b_kg   = tid >> 6;            // 0..3

    float acc[8][4];
#pragma unroll
    for (int i = 0; i < 8; i++)
#pragma unroll
        for (int j = 0; j < 4; j++) acc[i][j] = 0.0f;

    const bool bcol_ok = (m0 + b_mc) < M;

    for (int k0 = 0; k0 < Ktot; k0 += 16) {
        // A tile: 2 x float4 per thread (K is a multiple of 16, rows 16B aligned)
#pragma unroll
        for (int h = 0; h < 2; h++) {
            int row = a_row0 + h * 64;
            const float4 v = *reinterpret_cast<const float4*>(
                &Ad[(size_t)(n0 + row) * Ktot + k0 + a_kq]);
            As[a_kq + 0][row] = v.x;
            As[a_kq + 1][row] = v.y;
            As[a_kq + 2][row] = v.z;
            As[a_kq + 3][row] = v.w;
        }
        // B tile: 4 scalar loads per thread, coalesced across b_mc, M-guarded
#pragma unroll
        for (int h = 0; h < 4; h++) {
            int kr = b_kg + h * 4;
            Bs[kr][b_mc] = bcol_ok ? Wd[(size_t)(k0 + kr) * M + m0 + b_mc] : 0.0f;
        }
        __syncthreads();

#pragma unroll
        for (int kk = 0; kk < 16; kk++) {
            float4 b4 = *reinterpret_cast<const float4*>(&Bs[kk][tx * 4]);
            float4 a0 = *reinterpret_cast<const float4*>(&As[kk][ty * 8]);
            float4 a1 = *reinterpret_cast<const float4*>(&As[kk][ty * 8 + 4]);
            float a[8] = {a0.x, a0.y, a0.z, a0.w, a1.x, a1.y, a1.z, a1.w};
            float b[4] = {b4.x, b4.y, b4.z, b4.w};
#pragma unroll
            for (int i = 0; i < 8; i++)
#pragma unroll
                for (int j = 0; j < 4; j++)
                    acc[i][j] = fmaf(a[i], b[j], acc[i][j]);
        }
        __syncthreads();
    }

#pragma unroll
    for (int j = 0; j < 4; j++) {
        int col = m0 + tx * 4 + j;
        if (col < M) {
            float bv = bd[col];
#pragma unroll
            for (int i = 0; i < 8; i++) {
                float v = acc[i][j] + bv;
                if (act) v = tanhf(v);
                Cd[(size_t)(n0 + ty * 8 + i) * M + col] = v;
            }
        }
    }
}

// ---------------- kernel 3: rational-quadratic spline (one warp per (n,i)) --
__device__ __forceinline__ float softplusf(float v) {
    // matches jax.nn.softplus: max(v,0) + log1p(exp(-|v|))
    return fmaxf(v, 0.0f) + log1pf(expf(-fabsf(v)));
}
__device__ __forceinline__ float warp_max(float v) {
#pragma unroll
    for (int o = 16; o; o >>= 1) v = fmaxf(v, __shfl_xor_sync(0xffffffffu, v, o));
    return v;
}
__device__ __forceinline__ float warp_sum(float v) {
#pragma unroll
    for (int o = 16; o; o >>= 1) v += __shfl_xor_sync(0xffffffffu, v, o);
    return v;
}

__global__ void spline_kernel(const float* __restrict__ x, float* __restrict__ zout) {
    const unsigned FULL = 0xffffffffu;
    int warp_global = (blockIdx.x * blockDim.x + threadIdx.x) >> 5;  // = i*N + n
    int lane = threadIdx.x & 31;
    if (warp_global >= DIM * N_BATCH) return;
    int i = warp_global >> 13;
    int n = warp_global & (N_BATCH - 1);

    const float* row = g_O3 + (size_t)warp_global * M3;
    float uw  = row[lane];
    float uh  = row[32 + lane];
    float udv = (lane < 31) ? row[64 + lane] : 0.0f;

    // NOTE: reference applies softmax TWICE to widths/heights
    // (Wp = 6*softmax(out) is softmaxed again inside the RQS), and
    // softplus twice to derivatives.  Replicated exactly.
    // widths
    float m1 = warp_max(uw);
    float s1 = warp_sum(expf(uw - m1));
    float tW = 6.0f * (expf(uw - m1) / s1);
    float m2 = warp_max(tW);
    float e2 = expf(tW - m2);
    float s2 = warp_sum(e2);
    float wbin = 1e-3f + (1.0f - 32.0f * 1e-3f) * (e2 / s2);
    // heights
    float m3 = warp_max(uh);
    float s3 = warp_sum(expf(uh - m3));
    float tH = 6.0f * (expf(uh - m3) / s3);
    float m4 = warp_max(tH);
    float e4 = expf(tH - m4);
    float s4 = warp_sum(e4);
    float hbin = 1e-3f + (1.0f - 32.0f * 1e-3f) * (e4 / s4);

    // inclusive scans -> knot positions
    float Sw = wbin, Sh = hbin;
#pragma unroll
    for (int o = 1; o < 32; o <<= 1) {
        float t0 = __shfl_up_sync(FULL, Sw, o);
        float t1 = __shfl_up_sync(FULL, Sh, o);
        if (lane >= o) { Sw += t0; Sh += t1; }
    }
    float cwR = (lane == 31) ? 3.0f : fmaf(6.0f, Sw, -3.0f);
    float chR = (lane == 31) ? 3.0f : fmaf(6.0f, Sh, -3.0f);
    float cwL = __shfl_up_sync(FULL, cwR, 1); if (lane == 0) cwL = -3.0f;
    float chL = __shfl_up_sync(FULL, chR, 1); if (lane == 0) chL = -3.0f;
    float wdiff = cwR - cwL;
    float hdiff = chR - chL;

    // derivatives: boundary = exactly 1, interior = 1e-3 + softplus(softplus(raw))
    float dvi = 1e-3f + softplusf(softplusf(udv));
    float dhi = (lane < 31) ? dvi : 1.0f;
    float dlo = __shfl_up_sync(FULL, dvi, 1); if (lane == 0) dlo = 1.0f;

    float xv = x[n * DIM + i];
    float xc = fminf(fmaxf(xv, -3.0f), 3.0f);

    // bin index == #{l in 0..30 : xc >= right_knot(l)}  (matches searchsorted+eps)
    unsigned mask = __ballot_sync(FULL, (lane < 31) && (xc >= cwR));
    int idx = __popc(mask);

    float b_cwL = __shfl_sync(FULL, cwL,   idx);
    float b_w   = __shfl_sync(FULL, wdiff, idx);
    float b_chL = __shfl_sync(FULL, chL,   idx);
    float b_h   = __shfl_sync(FULL, hdiff, idx);
    float b_d0  = __shfl_sync(FULL, dlo,   idx);
    float b_d1  = __shfl_sync(FULL, dhi,   idx);
    float delta = b_h / b_w;

    float theta = (xc - b_cwL) / b_w;
    float t1m   = theta * (1.0f - theta);
    float th2   = theta * theta;
    float omt   = 1.0f - theta;
    float num   = b_h * (delta * th2 + b_d0 * t1m);
    float den   = delta + (b_d0 + b_d1 - 2.0f * delta) * t1m;
    float y     = b_chL + num / den;
    float dnum  = delta * delta * (b_d1 * th2 + 2.0f * delta * t1m + b_d0 * omt * omt);
    float ld    = logf(dnum) - 2.0f * logf(den);

    bool inside = (xv >= -3.0f) && (xv <= 3.0f);
    if (lane == 0) {
        zout[(size_t)n * DIM + i] = inside ? y : xv;
        g_LD[warp_global]         = inside ? ld : 0.0f;
    }
}

// ---------------- kernel 4: logdet reduction over dims ----------------------
__global__ void reduce_ld_kernel(float* __restrict__ ldout) {
    int n = blockIdx.x * blockDim.x + threadIdx.x;
    if (n >= N_BATCH) return;
    float s = 0.0f;
#pragma unroll
    for (int i = 0; i < DIM; i++) s += g_LD[i * N_BATCH + n];  // same order as reference
    ldout[n] = s;
}

// ---------------- launch ----------------------------------------------------
extern "C" void kernel_launch(void* const* d_in, const int* in_sizes, int n_in,
                              void* d_out, int out_size) {
    const float* x  = (const float*)d_in[0];
    const float* W1 = (const float*)d_in[1];   // [16][32][800]
    const float* b1 = (const float*)d_in[2];   // [16][800]
    const float* W2 = (const float*)d_in[3];   // [16][800][800]
    const float* b2 = (const float*)d_in[4];   // [16][800]
    const float* W3 = (const float*)d_in[5];   // [16][800][95]
    const float* b3 = (const float*)d_in[6];   // [16][95]
    float* out = (float*)d_out;                // [8192][16] z, then [8192] log_det

    float *F, *H1, *H2, *O3;
    cudaGetSymbolAddress((void**)&F,  g_F);
    cudaGetSymbolAddress((void**)&H1, g_H1);
    cudaGetSymbolAddress((void**)&H2, g_H2);
    cudaGetSymbolAddress((void**)&O3, g_O3);

    featurize_kernel<<<(DIM * N_BATCH * KB + 255) / 256, 256>>>(x);

    dim3 gHID((HID + 63) / 64, N_BATCH / 128, DIM);   // 13 x 64 x 16
    gemm_bias_act<<<gHID, 256>>>(F,  W1, b1, H1, KB,  HID, 1);
    gemm_bias_act<<<gHID, 256>>>(H1, W2, b2, H2, HID, HID, 1);

    dim3 gO3((M3 + 63) / 64, N_BATCH / 128, DIM);     // 2 x 64 x 16
    gemm_bias_act<<<gO3, 256>>>(H2, W3, b3, O3, HID, M3, 0);

    spline_kernel<<<(DIM * N_BATCH) / 8, 256>>>(x, out);           // 8 warps/block
    reduce_ld_kernel<<<N_BATCH / 256, 256>>>(out + (size_t)N_BATCH * DIM);
}

// round 16
// speedup vs baseline: 2.1521x; 2.1521x over previous
#include <cuda_runtime.h>
#include <math.h>
#include <cstdint>

#define N_BATCH 8192
#define DIM 16
#define HID 800
#define KB 32
#define M3 95   /* 3*K_BINS - 1 */

#define BM 128
#define BN 128
#define BK 16

// ---------------- scratch (static device allocations; no cudaMalloc) -------
static __device__ __align__(16) float g_F [(size_t)DIM * N_BATCH * KB];
static __device__ __align__(16) float g_H1[(size_t)DIM * N_BATCH * HID];
static __device__ __align__(16) float g_H2[(size_t)DIM * N_BATCH * HID];
static __device__ __align__(16) float g_O3[(size_t)DIM * N_BATCH * M3];
static __device__ float g_LD[DIM * N_BATCH];

// ---------------- mma.sync helpers (baseline PTX, no sm_103a features) -----
__device__ __forceinline__ uint32_t f2tf32(float x) {
    uint32_t r;
    asm("cvt.rna.tf32.f32 %0, %1;" : "=r"(r) : "f"(x));
    return r;
}
__device__ __forceinline__ void mma8(float* c, const uint32_t* a,
                                     uint32_t b0, uint32_t b1) {
    asm volatile(
        "mma.sync.aligned.m16n8k8.row.col.f32.tf32.tf32.f32 "
        "{%0,%1,%2,%3}, {%4,%5,%6,%7}, {%8,%9}, {%0,%1,%2,%3};"
        : "+f"(c[0]), "+f"(c[1]), "+f"(c[2]), "+f"(c[3])
        : "r"(a[0]), "r"(a[1]), "r"(a[2]), "r"(a[3]), "r"(b0), "r"(b1));
}

// ---------------- kernel: trig featurization --------------------------------
__global__ void featurize_kernel(const float* __restrict__ x) {
    int gid = blockIdx.x * blockDim.x + threadIdx.x;
    const int total = DIM * N_BATCH * KB;
    if (gid >= total) return;
    int j    = gid & 31;
    int rest = gid >> 5;
    int n    = rest & (N_BATCH - 1);
    int i    = rest >> 13;

    float v = 0.0f;
    const float PI = 3.14159265358979323846f;
    if (i == 0) {
        v = (j == 0) ? 1.0f : 0.0f;
    } else if (j < i) {
        v = cosf((PI * x[n * DIM + j]) / 3.0f);
    } else if (j < 2 * i) {
        v = sinf((PI * x[n * DIM + (j - i)]) / 3.0f);
    }
    g_F[gid] = v;
}

// ---------------- kernel: tf32 mma.sync batched GEMM ------------------------
// C[dim][n][m] = act( A[dim][n][:Ktot] . W[dim][:Ktot][m] + bias[dim][m] )
// A row-major [N_BATCH][Ktot]; W row-major [Ktot][N]; C row-major [N_BATCH][N].
// SMEM tiles stored in mma fragment order:
//   sA[buf][blk=mb*2+kb][slot][lane], slot = r8 + 2*c  (A frag reg order)
//   sB[buf][nb][j][lane],             j = kb*2 + c     (B frag reg order)
__global__ __launch_bounds__(256) void gemm_tc(
    const float* __restrict__ A, const float* __restrict__ W,
    const float* __restrict__ bias, float* __restrict__ C,
    int Ktot, int N, int act)
{
    __shared__ uint32_t sA[2][16][4][33];
    __shared__ uint32_t sB[2][16][4][33];

    const int tid  = threadIdx.x;
    const int lane = tid & 31;
    const int wid  = tid >> 5;
    const int wm   = wid & 3;    // 4 warp rows of 32
    const int wn   = wid >> 2;   // 2 warp cols of 64

    const int dimi = blockIdx.z;
    const int m0   = blockIdx.y * BM;
    const int n0   = blockIdx.x * BN;

    const float* Ad = A + ((size_t)dimi * N_BATCH + m0) * Ktot;
    const float* Wd = W + (size_t)dimi * Ktot * N;

    float acc[2][8][4];
#pragma unroll
    for (int mi = 0; mi < 2; mi++)
#pragma unroll
        for (int ni = 0; ni < 8; ni++)
#pragma unroll
            for (int s = 0; s < 4; s++) acc[mi][ni][s] = 0.0f;

    float4 av[2], bv[2];
    const bool nvec = ((N & 3) == 0);

    const int nk = Ktot / BK;

    // ---- ldg for chunk kc into av/bv
    auto ldg = [&](int kc) {
        const int k0 = kc * BK;
#pragma unroll
        for (int h = 0; h < 2; h++) {
            int f = tid + 256 * h;
            int m = f >> 2, kq = (f & 3) * 4;
            av[h] = *(const float4*)(Ad + (size_t)m * Ktot + k0 + kq);
        }
#pragma unroll
        for (int h = 0; h < 2; h++) {
            int f = tid + 256 * h;
            int kk = f >> 5, nq = (f & 31) * 4;
            int n = n0 + nq;
            const float* src = Wd + (size_t)(k0 + kk) * N + n;
            if (nvec && n < N) {
                bv[h] = *(const float4*)src;
            } else {
                bv[h].x = (n + 0 < N) ? src[0] : 0.0f;
                bv[h].y = (n + 1 < N) ? src[1] : 0.0f;
                bv[h].z = (n + 2 < N) ? src[2] : 0.0f;
                bv[h].w = (n + 3 < N) ? src[3] : 0.0f;
            }
        }
    };

    // ---- sts av/bv into buffer `buf` (fragment order, tf32-converted)
    auto sts = [&](int buf) {
#pragma unroll
        for (int h = 0; h < 2; h++) {
            int f = tid + 256 * h;
            int m = f >> 2, kq = (f & 3) * 4;
            int g = m & 7, r8 = (m >> 3) & 1, mb = m >> 4;
            float e[4] = {av[h].x, av[h].y, av[h].z, av[h].w};
#pragma unroll
            for (int ee = 0; ee < 4; ee++) {
                int k = kq + ee;
                int blk  = mb * 2 + (k >> 3);
                int slot = r8 + 2 * ((k >> 2) & 1);
                sA[buf][blk][slot][g * 4 + (k & 3)] = f2tf32(e[ee]);
            }
        }
#pragma unroll
        for (int h = 0; h < 2; h++) {
            int f = tid + 256 * h;
            int kk = f >> 5, nq = (f & 31) * 4;
            int j  = (kk >> 3) * 2 + ((kk >> 2) & 1);
            int t4 = kk & 3;
            float e[4] = {bv[h].x, bv[h].y, bv[h].z, bv[h].w};
#pragma unroll
            for (int ee = 0; ee < 4; ee++) {
                int n = nq + ee;
                sB[buf][n >> 3][j][(n & 7) * 4 + t4] = f2tf32(e[ee]);
            }
        }
    };

    // ---- compute one BK chunk from buffer `buf`
    auto comp = [&](int buf) {
        uint32_t a[2][2][4];
#pragma unroll
        for (int mi = 0; mi < 2; mi++)
#pragma unroll
            for (int kb = 0; kb < 2; kb++)
#pragma unroll
                for (int s = 0; s < 4; s++)
                    a[mi][kb][s] = sA[buf][(wm * 2 + mi) * 2 + kb][s][lane];
#pragma unroll
        for (int ni = 0; ni < 8; ni++) {
            uint32_t b0 = sB[buf][wn * 8 + ni][0][lane];
            uint32_t b1 = sB[buf][wn * 8 + ni][1][lane];
            uint32_t b2 = sB[buf][wn * 8 + ni][2][lane];
            uint32_t b3 = sB[buf][wn * 8 + ni][3][lane];
            mma8(acc[0][ni], a[0][0], b0, b1);
            mma8(acc[1][ni], a[1][0], b0, b1);
            mma8(acc[0][ni], a[0][1], b2, b3);
            mma8(acc[1][ni], a[1][1], b2, b3);
        }
    };

    // ---- pipelined mainloop (register double-buffer of next chunk)
    ldg(0);
    sts(0);
    __syncthreads();
    for (int kc = 0; kc < nk; kc++) {
        const int buf = kc & 1;
        if (kc + 1 < nk) ldg(kc + 1);
        comp(buf);
        if (kc + 1 < nk) sts(buf ^ 1);
        __syncthreads();
    }

    // ---- epilogue: bias + optional tanh, store
    const float* brow = bias + (size_t)dimi * N;
    const int g = lane >> 2, t4 = lane & 3;
    const bool even = ((N & 1) == 0);
#pragma unroll
    for (int ni = 0; ni < 8; ni++) {
        int colb = n0 + wn * 64 + ni * 8 + t4 * 2;
        float bv0 = (colb     < N) ? __ldg(brow + colb)     : 0.0f;
        float bv1 = (colb + 1 < N) ? __ldg(brow + colb + 1) : 0.0f;
#pragma unroll
        for (int mi = 0; mi < 2; mi++) {
#pragma unroll
            for (int r8 = 0; r8 < 2; r8++) {
                int row = m0 + wm * 32 + mi * 16 + r8 * 8 + g;
                float v0 = acc[mi][ni][r8 * 2 + 0] + bv0;
                float v1 = acc[mi][ni][r8 * 2 + 1] + bv1;
                if (act) { v0 = tanhf(v0); v1 = tanhf(v1); }
                float* Cr = C + ((size_t)dimi * N_BATCH + row) * N;
                if (even && colb + 1 < N) {
                    *(float2*)(Cr + colb) = make_float2(v0, v1);
                } else {
                    if (colb     < N) Cr[colb]     = v0;
                    if (colb + 1 < N) Cr[colb + 1] = v1;
                }
            }
        }
    }
}

// ---------------- kernel: rational-quadratic spline (one warp per (n,i)) ----
__device__ __forceinline__ float softplusf(float v) {
    return fmaxf(v, 0.0f) + log1pf(expf(-fabsf(v)));
}
__device__ __forceinline__ float warp_max(float v) {
#pragma unroll
    for (int o = 16; o; o >>= 1) v = fmaxf(v, __shfl_xor_sync(0xffffffffu, v, o));
    return v;
}
__device__ __forceinline__ float warp_sum(float v) {
#pragma unroll
    for (int o = 16; o; o >>= 1) v += __shfl_xor_sync(0xffffffffu, v, o);
    return v;
}

__global__ void spline_kernel(const float* __restrict__ x, float* __restrict__ zout) {
    const unsigned FULL = 0xffffffffu;
    int warp_global = (blockIdx.x * blockDim.x + threadIdx.x) >> 5;
    int lane = threadIdx.x & 31;
    if (warp_global >= DIM * N_BATCH) return;
    int i = warp_global >> 13;
    int n = warp_global & (N_BATCH - 1);

    const float* row = g_O3 + (size_t)warp_global * M3;
    float uw  = row[lane];
    float uh  = row[32 + lane];
    float udv = (lane < 31) ? row[64 + lane] : 0.0f;

    // reference applies softmax twice to widths/heights, softplus twice to derivs
    float m1 = warp_max(uw);
    float s1 = warp_sum(expf(uw - m1));
    float tW = 6.0f * (expf(uw - m1) / s1);
    float m2 = warp_max(tW);
    float e2 = expf(tW - m2);
    float s2 = warp_sum(e2);
    float wbin = 1e-3f + (1.0f - 32.0f * 1e-3f) * (e2 / s2);

    float m3 = warp_max(uh);
    float s3 = warp_sum(expf(uh - m3));
    float tH = 6.0f * (expf(uh - m3) / s3);
    float m4 = warp_max(tH);
    float e4 = expf(tH - m4);
    float s4 = warp_sum(e4);
    float hbin = 1e-3f + (1.0f - 32.0f * 1e-3f) * (e4 / s4);

    float Sw = wbin, Sh = hbin;
#pragma unroll
    for (int o = 1; o < 32; o <<= 1) {
        float t0 = __shfl_up_sync(FULL, Sw, o);
        float t1 = __shfl_up_sync(FULL, Sh, o);
        if (lane >= o) { Sw += t0; Sh += t1; }
    }
    float cwR = (lane == 31) ? 3.0f : fmaf(6.0f, Sw, -3.0f);
    float chR = (lane == 31) ? 3.0f : fmaf(6.0f, Sh, -3.0f);
    float cwL = __shfl_up_sync(FULL, cwR, 1); if (lane == 0) cwL = -3.0f;
    float chL = __shfl_up_sync(FULL, chR, 1); if (lane == 0) chL = -3.0f;
    float wdiff = cwR - cwL;
    float hdiff = chR - chL;

    float dvi = 1e-3f + softplusf(softplusf(udv));
    float dhi = (lane < 31) ? dvi : 1.0f;
    float dlo = __shfl_up_sync(FULL, dvi, 1); if (lane == 0) dlo = 1.0f;

    float xv = x[n * DIM + i];
    float xc = fminf(fmaxf(xv, -3.0f), 3.0f);

    unsigned mask = __ballot_sync(FULL, (lane < 31) && (xc >= cwR));
    int idx = __popc(mask);

    float b_cwL = __shfl_sync(FULL, cwL,   idx);
    float b_w   = __shfl_sync(FULL, wdiff, idx);
    float b_chL = __shfl_sync(FULL, chL,   idx);
    float b_h   = __shfl_sync(FULL, hdiff, idx);
    float b_d0  = __shfl_sync(FULL, dlo,   idx);
    float b_d1  = __shfl_sync(FULL, dhi,   idx);
    float delta = b_h / b_w;

    float theta = (xc - b_cwL) / b_w;
    float t1m   = theta * (1.0f - theta);
    float th2   = theta * theta;
    float omt   = 1.0f - theta;
    float num   = b_h * (delta * th2 + b_d0 * t1m);
    float den   = delta + (b_d0 + b_d1 - 2.0f * delta) * t1m;
    float y     = b_chL + num / den;
    float dnum  = delta * delta * (b_d1 * th2 + 2.0f * delta * t1m + b_d0 * omt * omt);
    float ld    = logf(dnum) - 2.0f * logf(den);

    bool inside = (xv >= -3.0f) && (xv <= 3.0f);
    if (lane == 0) {
        zout[(size_t)n * DIM + i] = inside ? y : xv;
        g_LD[warp_global]         = inside ? ld : 0.0f;
    }
}

// ---------------- kernel: logdet reduction ----------------------------------
__global__ void reduce_ld_kernel(float* __restrict__ ldout) {
    int n = blockIdx.x * blockDim.x + threadIdx.x;
    if (n >= N_BATCH) return;
    float s = 0.0f;
#pragma unroll
    for (int i = 0; i < DIM; i++) s += g_LD[i * N_BATCH + n];
    ldout[n] = s;
}

// ---------------- launch ----------------------------------------------------
extern "C" void kernel_launch(void* const* d_in, const int* in_sizes, int n_in,
                              void* d_out, int out_size) {
    const float* x  = (const float*)d_in[0];
    const float* W1 = (const float*)d_in[1];   // [16][32][800]
    const float* b1 = (const float*)d_in[2];   // [16][800]
    const float* W2 = (const float*)d_in[3];   // [16][800][800]
    const float* b2 = (const float*)d_in[4];   // [16][800]
    const float* W3 = (const float*)d_in[5];   // [16][800][95]
    const float* b3 = (const float*)d_in[6];   // [16][95]
    float* out = (float*)d_out;

    float *F, *H1, *H2, *O3;
    cudaGetSymbolAddress((void**)&F,  g_F);
    cudaGetSymbolAddress((void**)&H1, g_H1);
    cudaGetSymbolAddress((void**)&H2, g_H2);
    cudaGetSymbolAddress((void**)&O3, g_O3);

    featurize_kernel<<<(DIM * N_BATCH * KB + 255) / 256, 256>>>(x);

    dim3 g12((HID + BN - 1) / BN, N_BATCH / BM, DIM);   // 7 x 64 x 16
    gemm_tc<<<g12, 256>>>(F,  W1, b1, H1, KB,  HID, 1);
    gemm_tc<<<g12, 256>>>(H1, W2, b2, H2, HID, HID, 1);

    dim3 g3((M3 + BN - 1) / BN, N_BATCH / BM, DIM);     // 1 x 64 x 16
    gemm_tc<<<g3, 256>>>(H2, W3, b3, O3, HID, M3, 0);

    spline_kernel<<<(DIM * N_BATCH) / 8, 256>>>(x, out);
    reduce_ld_kernel<<<N_BATCH / 256, 256>>>(out + (size_t)N_BATCH * DIM);
}